// round 2
// baseline (speedup 1.0000x reference)
#include <cuda_runtime.h>
#include <cstdint>

#define T_STEPS 2048
#define BATCH   1024
#define INPUT   4
#define HID     10
#define OUTF    4
#define CHUNK   16          // timesteps staged per cp.async chunk
#define BPB     8           // batches per block (4 warps * 2)
#define THREADS 128

__device__ __forceinline__ float sigf(float x) {
    // 1/(1+e^-x); e^-x -> inf for very negative x -> 0, correct limit
    return __fdividef(1.0f, 1.0f + __expf(-x));
}
__device__ __forceinline__ float tanh_fast(float x) {
    // tanh(x) = 1 - 2/(e^{2x}+1); saturates correctly at +-1
    float e = __expf(2.0f * x);
    return 1.0f - __fdividef(2.0f, e + 1.0f);
}

__device__ __forceinline__ void cp_async16(void* dst, const void* src) {
    unsigned d = (unsigned)__cvta_generic_to_shared(dst);
    asm volatile("cp.async.ca.shared.global [%0], [%1], 16;\n" :: "r"(d), "l"(src));
}
__device__ __forceinline__ void cp_commit() {
    asm volatile("cp.async.commit_group;\n" ::: "memory");
}
__device__ __forceinline__ void cp_wait1() {
    asm volatile("cp.async.wait_group 1;\n" ::: "memory");
}

__global__ void __launch_bounds__(THREADS, 1)
lstm_persistent_kernel(const float* __restrict__ x,
                       const float* __restrict__ h0,
                       const float* __restrict__ c0,
                       const float* __restrict__ W_ih,
                       const float* __restrict__ W_hh,
                       const float* __restrict__ b_ih,
                       const float* __restrict__ b_hh,
                       const float* __restrict__ W_fc,
                       const float* __restrict__ b_fc,
                       float* __restrict__ out,
                       int write_state)
{
    __shared__ float4 sx[2][CHUNK][BPB];

    const int tid  = threadIdx.x;
    const int warp = tid >> 5;
    const int lane = tid & 31;
    const int half = lane >> 4;      // 0 or 1: which batch in the warp
    const int jj   = lane & 15;      // lane id within 16-lane group
    const int j    = (jj < HID) ? jj : (HID - 1);  // clamped hidden index

    const int gbase = blockIdx.x * BPB;
    const int bb    = warp * 2 + half;         // batch index within block 0..7
    const int batch = gbase + bb;              // global batch 0..1023

    // ---- load per-lane weights into registers (once) ----
    float wih[4][INPUT], whh[4][HID], bias[4];
#pragma unroll
    for (int g = 0; g < 4; g++) {
        const int row = g * HID + j;
#pragma unroll
        for (int i = 0; i < INPUT; i++) wih[g][i] = W_ih[row * INPUT + i];
#pragma unroll
        for (int k = 0; k < HID; k++)   whh[g][k] = W_hh[row * HID + k];
        bias[g] = b_ih[row] + b_hh[row];
    }
    const int jo = (jj < OUTF) ? jj : 0;
    float wfc[HID], bfc = b_fc[jo];
#pragma unroll
    for (int k = 0; k < HID; k++) wfc[k] = W_fc[jo * HID + k];

    // ---- state ----
    float h_all[HID];
#pragma unroll
    for (int k = 0; k < HID; k++) h_all[k] = h0[batch * HID + k];
    float c = c0[batch * HID + j];

    const float4* x4 = reinterpret_cast<const float4*>(x);
    const int tt = tid >> 3;   // 0..15 : timestep within chunk
    const int bx = tid & 7;    // 0..7  : batch within block

    // prefetch chunk 0
    cp_async16(&sx[0][tt][bx], x4 + (size_t)(0 * CHUNK + tt) * BATCH + gbase + bx);
    cp_commit();

    const int NCH = T_STEPS / CHUNK;   // 128
    for (int ch = 0; ch < NCH; ch++) {
        if (ch + 1 < NCH) {
            cp_async16(&sx[(ch + 1) & 1][tt][bx],
                       x4 + (size_t)((ch + 1) * CHUNK + tt) * BATCH + gbase + bx);
        }
        cp_commit();
        cp_wait1();          // chunk `ch` resident
        __syncthreads();

        const int buf = ch & 1;
#pragma unroll 2
        for (int s = 0; s < CHUNK; s++) {
            const float4 xv = sx[buf][s][bb];

            float gate[4];
#pragma unroll
            for (int g = 0; g < 4; g++) {
                // two accumulators to halve the dependency chain
                float a  = fmaf(xv.x, wih[g][0], bias[g]);
                float b2 = xv.y * wih[g][1];
                a  = fmaf(xv.z, wih[g][2], a);
                b2 = fmaf(xv.w, wih[g][3], b2);
#pragma unroll
                for (int k = 0; k < HID; k += 2) {
                    a  = fmaf(h_all[k],     whh[g][k],     a);
                    b2 = fmaf(h_all[k + 1], whh[g][k + 1], b2);
                }
                gate[g] = a + b2;
            }

            const float ig = sigf(gate[0]);
            const float fg = sigf(gate[1]);
            const float gg = tanh_fast(gate[2]);
            const float og = sigf(gate[3]);

            c = fmaf(fg, c, ig * gg);
            const float hn = og * tanh_fast(c);

            // broadcast new h across the 16-lane group (serves FC now and gates next step)
#pragma unroll
            for (int k = 0; k < HID; k++)
                h_all[k] = __shfl_sync(0xffffffffu, hn, k, 16);

            if (jj < OUTF) {
                float a  = bfc;
                float b2 = 0.0f;
#pragma unroll
                for (int k = 0; k < HID; k += 2) {
                    a  = fmaf(h_all[k],     wfc[k],     a);
                    b2 = fmaf(h_all[k + 1], wfc[k + 1], b2);
                }
                const int t = ch * CHUNK + s;
                out[((size_t)t * BATCH + batch) * OUTF + jj] = a + b2;
            }
        }
        __syncthreads();   // everyone done with buf before it gets overwritten
    }

    // ---- final states (hT, cT) appended after `out` in the flattened pytree ----
    if (write_state && jj < HID) {
        const size_t off = (size_t)T_STEPS * BATCH * OUTF;
        out[off + (size_t)batch * HID + jj] = h_all[jj];
        out[off + (size_t)BATCH * HID + (size_t)batch * HID + jj] = c;
    }
}

extern "C" void kernel_launch(void* const* d_in, const int* in_sizes, int n_in,
                              void* d_out, int out_size) {
    const float* x    = (const float*)d_in[0];
    const float* h0   = (const float*)d_in[1];
    const float* c0   = (const float*)d_in[2];
    const float* W_ih = (const float*)d_in[3];
    const float* W_hh = (const float*)d_in[4];
    const float* b_ih = (const float*)d_in[5];
    const float* b_hh = (const float*)d_in[6];
    const float* W_fc = (const float*)d_in[7];
    const float* b_fc = (const float*)d_in[8];
    float* out = (float*)d_out;

    const long long need_state = (long long)T_STEPS * BATCH * OUTF + 2LL * BATCH * HID;
    const int write_state = (out_size >= need_state) ? 1 : 0;

    lstm_persistent_kernel<<<BATCH / BPB, THREADS>>>(
        x, h0, c0, W_ih, W_hh, b_ih, b_hh, W_fc, b_fc, out, write_state);
}